// round 6
// baseline (speedup 1.0000x reference)
#include <cuda_runtime.h>
#include <cstdint>

// GateRecurrent2dnoind: H[:,:,h,w] = B*X + G1*H[h-1,w-1] + G2*H[h,w-1] + G3*H[h+1,w-1]
// (8, 96, 128, 128) -> 768 independent (128 x 128) planes, serial scan over W.
//
// R6 == R5 resubmit (round 5 died to container infra, no metrics). Design:
// register-carry recurrence (warp 0 computes, 4 rows/lane, 2 shfls/step, no
// per-step barrier) tuned for OCCUPANCY: chunk width = 8 columns so staged
// smem is 45KB/block -> 5 blocks/SM -> 5 planes in flight/SM, 1.04 waves
// (R4 was stuck at 2 blocks/SM, occ 6.1%, DRAM 57%).
//   - paired-row smem layout (one 16-float smem row = two real 8-float rows)
//     keeps 4 granules/row so the XOR swizzle (<=4-way conflicts) still works.
//   - cooperative cp.async loader / staged store keep full-sector accesses.
//   - 2-deep chunk pipeline, 2 barriers per chunk (32/plane).

#define H_DIM   128
#define W_DIM   128
#define CW      8                       // chunk width (columns)
#define NCH     (W_DIM / CW)            // 16
#define NARR    5
#define TILE_Q  256                     // 16B granules per array tile (64 srows x 4)
#define NTHR    64

__device__ __forceinline__ void cp_async16(uint32_t dst, const float* src) {
    asm volatile("cp.async.cg.shared.global [%0], [%1], 16;\n" :: "r"(dst), "l"(src));
}
__device__ __forceinline__ void cp_commit() {
    asm volatile("cp.async.commit_group;\n" ::: "memory");
}
template <int N>
__device__ __forceinline__ void cp_wait() {
    asm volatile("cp.async.wait_group %0;\n" :: "n"(N) : "memory");
}

// Granule index of (srow, q). srow packs two real rows: r = 2*srow + (q>>1),
// col4 = q&1. Swizzle XORs q with (srow>>1)&3 to decorrelate banks for the
// compute warp's stride-2 srow access.
__device__ __forceinline__ int g_idx(int srow, int q) {
    return srow * 4 + (q ^ ((srow >> 1) & 3));
}

__global__ void __launch_bounds__(NTHR, 5)
gaterec_kernel(const float* __restrict__ X,  const float* __restrict__ B,
               const float* __restrict__ G1, const float* __restrict__ G2,
               const float* __restrict__ G3, float* __restrict__ Out)
{
    extern __shared__ float4 smem4[];
    float4* in4  = smem4;                       // [2][NARR][TILE_Q]
    float4* out4 = smem4 + 2 * NARR * TILE_Q;   // [TILE_Q]

    const int t = threadIdx.x;
    const size_t plane = (size_t)blockIdx.x * (H_DIM * W_DIM);

    const float* srcs[NARR] = { X + plane, B + plane, G1 + plane, G2 + plane, G3 + plane };

    const uint32_t smem_u32 = (uint32_t)__cvta_generic_to_shared(in4);

    // Cooperative loader: per array 4 cp.async16/thread. Each warp instruction
    // covers 8 srows = 16 consecutive real rows, 32B per row (full sectors).
    auto load_chunk = [&](int c, int s) {
        const int cb = c * CW;
        #pragma unroll
        for (int a = 0; a < NARR; ++a) {
            const float* src = srcs[a];
            const uint32_t base = smem_u32 + (uint32_t)((s * NARR + a) * TILE_Q) * 16u;
            #pragma unroll
            for (int i = 0; i < 4; ++i) {
                int j    = t + NTHR * i;
                int srow = j >> 2;
                int q    = j & 3;
                int r    = 2 * srow + (q >> 1);
                cp_async16(base + (uint32_t)g_idx(srow, q) * 16u,
                           src + r * W_DIM + cb + (q & 1) * 4);
            }
        }
    };

    load_chunk(0, 0); cp_commit();
    load_chunk(1, 1); cp_commit();

    const int lane = t & 31;

    float cc0 = 0.f, cc1 = 0.f, cc2 = 0.f, cc3 = 0.f;   // carry column H[:, w-1]

    for (int c = 0; c < NCH; ++c) {
        cp_wait<1>();
        __syncthreads();                        // chunk c visible to everyone

        if (t < 32) {                           // warp 0: serial recurrence
            const float4* tb = in4 + (c & 1) * NARR * TILE_Q;

            #pragma unroll
            for (int gcol = 0; gcol < 2; ++gcol) {      // two 4-column groups
                int idxk[4];
                #pragma unroll
                for (int k = 0; k < 4; ++k) {
                    int srow = 2 * lane + (k >> 1);
                    int q    = ((k & 1) << 1) | gcol;
                    idxk[k]  = srow * 4 + (q ^ (lane & 3));  // (srow>>1)&3 == lane&3
                }

                float xv[4][4], bv[4][4], g1v[4][4], g2v[4][4], g3v[4][4];
                #pragma unroll
                for (int k = 0; k < 4; ++k) {
                    float4 v;
                    v = tb[0 * TILE_Q + idxk[k]];
                    xv[k][0]=v.x;  xv[k][1]=v.y;  xv[k][2]=v.z;  xv[k][3]=v.w;
                    v = tb[1 * TILE_Q + idxk[k]];
                    bv[k][0]=v.x;  bv[k][1]=v.y;  bv[k][2]=v.z;  bv[k][3]=v.w;
                    v = tb[2 * TILE_Q + idxk[k]];
                    g1v[k][0]=v.x; g1v[k][1]=v.y; g1v[k][2]=v.z; g1v[k][3]=v.w;
                    v = tb[3 * TILE_Q + idxk[k]];
                    g2v[k][0]=v.x; g2v[k][1]=v.y; g2v[k][2]=v.z; g2v[k][3]=v.w;
                    v = tb[4 * TILE_Q + idxk[k]];
                    g3v[k][0]=v.x; g3v[k][1]=v.y; g3v[k][2]=v.z; g3v[k][3]=v.w;
                }

                float ov[4][4];
                #pragma unroll
                for (int i = 0; i < 4; ++i) {
                    float up = __shfl_up_sync(0xffffffffu, cc3, 1);
                    if (lane == 0)  up = 0.f;
                    float dn = __shfl_down_sync(0xffffffffu, cc0, 1);
                    if (lane == 31) dn = 0.f;

                    float n0 = fmaf(g1v[0][i], up,
                               fmaf(g3v[0][i], cc1,
                               fmaf(bv[0][i],  xv[0][i], g2v[0][i] * cc0)));
                    float n1 = fmaf(g1v[1][i], cc0,
                               fmaf(g3v[1][i], cc2,
                               fmaf(bv[1][i],  xv[1][i], g2v[1][i] * cc1)));
                    float n2 = fmaf(g1v[2][i], cc1,
                               fmaf(g3v[2][i], cc3,
                               fmaf(bv[2][i],  xv[2][i], g2v[2][i] * cc2)));
                    float n3 = fmaf(g1v[3][i], cc2,
                               fmaf(g3v[3][i], dn,
                               fmaf(bv[3][i],  xv[3][i], g2v[3][i] * cc3)));

                    cc0 = n0; cc1 = n1; cc2 = n2; cc3 = n3;
                    ov[0][i] = n0; ov[1][i] = n1; ov[2][i] = n2; ov[3][i] = n3;
                }

                #pragma unroll
                for (int k = 0; k < 4; ++k)
                    out4[idxk[k]] = make_float4(ov[k][0], ov[k][1], ov[k][2], ov[k][3]);
            }
        }
        __syncthreads();                        // out tile ready; stage consumed

        // Cooperative coalesced store (same paired-row mapping as loader).
        {
            float* dst = Out + plane + (size_t)c * CW;
            #pragma unroll
            for (int i = 0; i < 4; ++i) {
                int j    = t + NTHR * i;
                int srow = j >> 2;
                int q    = j & 3;
                int r    = 2 * srow + (q >> 1);
                float4 v = out4[g_idx(srow, q)];
                *(float4*)(dst + r * W_DIM + (q & 1) * 4) = v;
            }
        }

        if (c + 2 < NCH) load_chunk(c + 2, c & 1);
        cp_commit();
    }
}

extern "C" void kernel_launch(void* const* d_in, const int* in_sizes, int n_in,
                              void* d_out, int out_size) {
    const float* X  = (const float*)d_in[0];
    const float* B  = (const float*)d_in[1];
    const float* G1 = (const float*)d_in[2];
    const float* G2 = (const float*)d_in[3];
    const float* G3 = (const float*)d_in[4];
    float* Out = (float*)d_out;

    const int planes = in_sizes[0] / (H_DIM * W_DIM);        // N*C = 768
    const int dyn_smem = (2 * NARR * TILE_Q + TILE_Q) * 16;  // 45,056 B -> 5 blocks/SM

    cudaFuncSetAttribute(gaterec_kernel,
                         cudaFuncAttributeMaxDynamicSharedMemorySize, dyn_smem);

    gaterec_kernel<<<planes, NTHR, dyn_smem>>>(X, B, G1, G2, G3, Out);
}